// round 3
// baseline (speedup 1.0000x reference)
#include <cuda_runtime.h>
#include <math.h>

#define B_  4
#define S_  2048
#define D_  1280
#define H_  16
#define HD_ 80
#define NQKV (3 * H_ * HD_)   // 3840

// Scratch (allocation-free rule: __device__ globals)
__device__ float g_qkv[(size_t)B_ * S_ * NQKV];        // 126 MB
__device__ float g_attn[(size_t)B_ * S_ * H_ * HD_];   // 42 MB
__device__ float g_qscale[HD_];

// ---------------------------------------------------------------------------
// Per-dim query scale: softplus(scaling) * log2(e) / sqrt(HD)
// ---------------------------------------------------------------------------
__global__ void qscale_kernel(const float* __restrict__ scaling) {
    int i = threadIdx.x;
    if (i < HD_) {
        float x = scaling[i];
        float sp = (x > 20.f) ? x : log1pf(expf(x));
        g_qscale[i] = sp * 1.4426950408889634f * rsqrtf((float)HD_);
    }
}

// ---------------------------------------------------------------------------
// SGEMM: C[m,n] = sum_k A[m,k] * B[n,k] + bias[n]   (both K-major)
// 128x128 block tile, KT=16, 256 threads, 8x8 microtile.
// APPLY_QSCALE: multiply columns n < H*HD (the Q block) by g_qscale[n % HD].
// M,N multiples of 128; K multiple of 16 (true for all uses here).
// ---------------------------------------------------------------------------
template <int APPLY_QSCALE>
__global__ __launch_bounds__(256, 2)
void gemm_tn(const float* __restrict__ A, const float* __restrict__ Bm,
             const float* __restrict__ bias, float* __restrict__ C,
             int M, int N, int K) {
    __shared__ float As[16][132];
    __shared__ float Bs[16][132];

    const int tid = threadIdx.x;
    const int m0 = blockIdx.y * 128;
    const int n0 = blockIdx.x * 128;
    const int ty = tid >> 4;      // 0..15
    const int tx = tid & 15;      // 0..15
    const int lrow = tid >> 1;    // 0..127 (loader row)
    const int lc4  = (tid & 1) * 2;

    float acc[8][8];
#pragma unroll
    for (int i = 0; i < 8; ++i)
#pragma unroll
        for (int j = 0; j < 8; ++j) acc[i][j] = 0.f;

    for (int k0 = 0; k0 < K; k0 += 16) {
#pragma unroll
        for (int q = 0; q < 2; ++q) {
            const int c4 = lc4 + q;
            float4 a = *(const float4*)&A[(size_t)(m0 + lrow) * K + k0 + c4 * 4];
            As[c4 * 4 + 0][lrow] = a.x;
            As[c4 * 4 + 1][lrow] = a.y;
            As[c4 * 4 + 2][lrow] = a.z;
            As[c4 * 4 + 3][lrow] = a.w;
            float4 b = *(const float4*)&Bm[(size_t)(n0 + lrow) * K + k0 + c4 * 4];
            Bs[c4 * 4 + 0][lrow] = b.x;
            Bs[c4 * 4 + 1][lrow] = b.y;
            Bs[c4 * 4 + 2][lrow] = b.z;
            Bs[c4 * 4 + 3][lrow] = b.w;
        }
        __syncthreads();

#pragma unroll
        for (int kk = 0; kk < 16; ++kk) {
            float a[8], b[8];
            *(float4*)&a[0] = *(const float4*)&As[kk][ty * 8];
            *(float4*)&a[4] = *(const float4*)&As[kk][ty * 8 + 4];
            *(float4*)&b[0] = *(const float4*)&Bs[kk][tx * 8];
            *(float4*)&b[4] = *(const float4*)&Bs[kk][tx * 8 + 4];
#pragma unroll
            for (int i = 0; i < 8; ++i)
#pragma unroll
                for (int j = 0; j < 8; ++j) acc[i][j] += a[i] * b[j];
        }
        __syncthreads();
    }

    // Epilogue: + bias, optional Q scaling, float4 stores
    float bb[8], qs[8];
#pragma unroll
    for (int j = 0; j < 8; ++j) {
        int n = n0 + tx * 8 + j;
        bb[j] = bias[n];
        qs[j] = 1.f;
        if (APPLY_QSCALE && n < H_ * HD_) qs[j] = g_qscale[n % HD_];
    }
#pragma unroll
    for (int i = 0; i < 8; ++i) {
        int m = m0 + ty * 8 + i;
        float o[8];
#pragma unroll
        for (int j = 0; j < 8; ++j) o[j] = (acc[i][j] + bb[j]) * qs[j];
        *(float4*)&C[(size_t)m * N + n0 + tx * 8]     = make_float4(o[0], o[1], o[2], o[3]);
        *(float4*)&C[(size_t)m * N + n0 + tx * 8 + 4] = make_float4(o[4], o[5], o[6], o[7]);
    }
}

// ---------------------------------------------------------------------------
// Causal flash attention, fp32. One thread per query row (online softmax is
// thread-local: no cross-thread reductions). BQ=128 queries/block, BK=32 keys
// per tile. Q/K/V read from g_qkv ([b,s,3*H*HD] layout, Q already scaled).
// Output (acc/l) written to g_attn [b,s,H*HD].
// grid = (S/128 [reversed for load balance], H, B), block = 128.
// ---------------------------------------------------------------------------
__global__ __launch_bounds__(128, 3)
void flash_kernel() {
    extern __shared__ float smem[];
    float4* q_s = (float4*)smem;        // [128][21] (20 used + pad)
    float4* k_s = q_s + 128 * 21;       // [32][21]
    float4* v_s = k_s + 32 * 21;        // [32][21]

    const int t  = threadIdx.x;
    const int qt = gridDim.x - 1 - blockIdx.x;   // heavy (high q0) blocks first
    const int q0 = qt * 128;
    const int h  = blockIdx.y;
    const int b  = blockIdx.z;

    const float4* qkv4 = (const float4*)g_qkv;   // row stride NQKV/4 = 960

    // Load Q tile (128 rows x 20 float4)
    for (int i = t; i < 128 * 20; i += 128) {
        int r = i / 20, c = i % 20;
        q_s[r * 21 + c] = qkv4[(size_t)(b * S_ + q0 + r) * 960 + h * 20 + c];
    }

    const int qi = q0 + t;
    float m = -INFINITY, l = 0.f;
    float4 acc[20];
#pragma unroll
    for (int d = 0; d < 20; ++d) acc[d] = make_float4(0.f, 0.f, 0.f, 0.f);

    for (int k0 = 0; k0 < q0 + 128; k0 += 32) {
        __syncthreads();   // protect previous tile's readers (and first-iter Q)
        // Load K,V tiles (32 rows x 20 float4 each)
        for (int i = t; i < 32 * 20; i += 128) {
            int r = i / 20, c = i % 20;
            size_t base = (size_t)(b * S_ + k0 + r) * 960 + h * 20 + c;
            k_s[r * 21 + c] = qkv4[base + 320];   // K block offset = H*HD/4
            v_s[r * 21 + c] = qkv4[base + 640];   // V block offset = 2*H*HD/4
        }
        __syncthreads();

        if (k0 <= qi) {
            float sc[32];
#pragma unroll
            for (int j = 0; j < 32; ++j) sc[j] = 0.f;
#pragma unroll 4
            for (int d = 0; d < 20; ++d) {
                float4 q4 = q_s[t * 21 + d];
#pragma unroll
                for (int j = 0; j < 32; ++j) {
                    float4 k4 = k_s[j * 21 + d];
                    sc[j] += q4.x * k4.x + q4.y * k4.y;
                    sc[j] += q4.z * k4.z + q4.w * k4.w;
                }
            }
            float tmax = -INFINITY;
#pragma unroll
            for (int j = 0; j < 32; ++j) {
                if (k0 + j > qi) sc[j] = -INFINITY;   // causal mask
                tmax = fmaxf(tmax, sc[j]);
            }
            float m_new = fmaxf(m, tmax);
            float corr = __expf(m - m_new);
            float lsum = 0.f;
#pragma unroll
            for (int j = 0; j < 32; ++j) {
                float p = __expf(sc[j] - m_new);   // exp(-inf)=0 handles mask
                sc[j] = p;
                lsum += p;
            }
            l = l * corr + lsum;
            m = m_new;
#pragma unroll
            for (int d = 0; d < 20; ++d) {
                acc[d].x *= corr; acc[d].y *= corr;
                acc[d].z *= corr; acc[d].w *= corr;
            }
#pragma unroll 4
            for (int j = 0; j < 32; ++j) {
                float p = sc[j];
#pragma unroll
                for (int d = 0; d < 20; ++d) {
                    float4 v4 = v_s[j * 21 + d];
                    acc[d].x += p * v4.x; acc[d].y += p * v4.y;
                    acc[d].z += p * v4.z; acc[d].w += p * v4.w;
                }
            }
        }
    }

    const float inv = 1.f / l;
    float4* out4 = (float4*)g_attn;   // row stride H*HD/4 = 320
    size_t obase = (size_t)(b * S_ + qi) * 320 + h * 20;
#pragma unroll
    for (int d = 0; d < 20; ++d) {
        out4[obase + d] = make_float4(acc[d].x * inv, acc[d].y * inv,
                                      acc[d].z * inv, acc[d].w * inv);
    }
}

// ---------------------------------------------------------------------------
// Launch
// ---------------------------------------------------------------------------
extern "C" void kernel_launch(void* const* d_in, const int* in_sizes, int n_in,
                              void* d_out, int out_size) {
    const float* hidden  = (const float*)d_in[0];
    // d_in[1] = attention_mask: pure causal, implemented structurally
    const float* scaling = (const float*)d_in[2];
    const float* qkv_w   = (const float*)d_in[3];
    const float* qkv_b   = (const float*)d_in[4];
    const float* o_w     = (const float*)d_in[5];
    const float* o_b     = (const float*)d_in[6];
    float* out = (float*)d_out;

    void* p_qkv = nullptr;
    void* p_attn = nullptr;
    cudaGetSymbolAddress(&p_qkv, g_qkv);
    cudaGetSymbolAddress(&p_attn, g_attn);

    qscale_kernel<<<1, 128>>>(scaling);

    // QKV projection: [8192,1280] x [3840,1280]^T (+bias, Q-scale epilogue)
    gemm_tn<1><<<dim3(NQKV / 128, (B_ * S_) / 128), 256>>>(
        hidden, qkv_w, qkv_b, (float*)p_qkv, B_ * S_, NQKV, D_);

    // Causal flash attention
    const int smem_bytes = (128 * 21 + 32 * 21 + 32 * 21) * 16;  // 64512 B
    cudaFuncSetAttribute(flash_kernel,
                         cudaFuncAttributeMaxDynamicSharedMemorySize, smem_bytes);
    flash_kernel<<<dim3(S_ / 128, H_, B_), 128, smem_bytes>>>();

    // Output projection: [8192,1280] x [1280,1280]^T (+bias)
    gemm_tn<0><<<dim3(D_ / 128, (B_ * S_) / 128), 256>>>(
        (const float*)p_attn, o_w, o_b, out, B_ * S_, D_, D_);
}

// round 4
// speedup vs baseline: 1.4680x; 1.4680x over previous
#include <cuda_runtime.h>
#include <math.h>

#define B_  4
#define S_  2048
#define D_  1280
#define H_  16
#define HD_ 80
#define NQKV (3 * H_ * HD_)   // 3840

// Scratch (allocation-free rule: __device__ globals)
__device__ float g_qkv[(size_t)B_ * S_ * NQKV];        // 126 MB
__device__ float g_attn[(size_t)B_ * S_ * H_ * HD_];   // 42 MB
__device__ float g_qscale[HD_];

// ---------------------------------------------------------------------------
// Per-dim query scale: softplus(scaling) * log2(e) / sqrt(HD)
// ---------------------------------------------------------------------------
__global__ void qscale_kernel(const float* __restrict__ scaling) {
    int i = threadIdx.x;
    if (i < HD_) {
        float x = scaling[i];
        float sp = (x > 20.f) ? x : log1pf(expf(x));
        g_qscale[i] = sp * 1.4426950408889634f * rsqrtf((float)HD_);
    }
}

// ---------------------------------------------------------------------------
// TF32 tensor-core GEMM: C[m,n] = sum_k A[m,k]*B[n,k] + bias[n]
// Both operands K-major. 128x128 block tile, KT=16, 256 threads (8 warps,
// 4m x 2n), warp tile 32x64, mma.sync.m16n8k8.tf32. Register-prefetch
// double buffering. Smem stride 136 -> conflict-free fragment LDS.
// M,N multiples of 128; K multiple of 16.
// ---------------------------------------------------------------------------
__device__ __forceinline__ unsigned f2tf(float x) {
    unsigned r;
    asm("cvt.rna.tf32.f32 %0, %1;" : "=r"(r) : "f"(x));
    return r;
}

__device__ __forceinline__ void mma_tf32(float* d, const unsigned* a,
                                         unsigned b0, unsigned b1) {
    asm volatile(
        "mma.sync.aligned.m16n8k8.row.col.f32.tf32.tf32.f32 "
        "{%0,%1,%2,%3}, {%4,%5,%6,%7}, {%8,%9}, {%0,%1,%2,%3};"
        : "+f"(d[0]), "+f"(d[1]), "+f"(d[2]), "+f"(d[3])
        : "r"(a[0]), "r"(a[1]), "r"(a[2]), "r"(a[3]), "r"(b0), "r"(b1));
}

#define SMS 136   // smem row stride (floats): (8c+g) banks all distinct

template <int APPLY_QSCALE>
__global__ __launch_bounds__(256, 2)
void gemm_tf32(const float* __restrict__ A, const float* __restrict__ Bm,
               const float* __restrict__ bias, float* __restrict__ C,
               int M, int N, int K) {
    __shared__ float As[16 * SMS];   // [k][m]
    __shared__ float Bs[16 * SMS];   // [k][n]

    const int tid  = threadIdx.x;
    const int lane = tid & 31;
    const int wid  = tid >> 5;
    const int wm   = wid & 3;        // warp row (x32)
    const int wn   = wid >> 2;       // warp col (x64)
    const int g    = lane >> 2;      // groupID 0..7
    const int c    = lane & 3;       // threadID_in_group 0..3

    const int m0 = blockIdx.y * 128;
    const int n0 = blockIdx.x * 128;

    const int lrow = tid >> 1;       // 0..127
    const int lc   = (tid & 1) * 8;  // k offset 0 or 8

    const float* Ap = A  + (size_t)(m0 + lrow) * K + lc;
    const float* Bp = Bm + (size_t)(n0 + lrow) * K + lc;

    float acc[2][8][4];
#pragma unroll
    for (int i = 0; i < 2; ++i)
#pragma unroll
        for (int j = 0; j < 8; ++j)
#pragma unroll
            for (int q = 0; q < 4; ++q) acc[i][j][q] = 0.f;

    // prefetch first tile into registers
    float4 pa0 = *(const float4*)(Ap + 0);
    float4 pa1 = *(const float4*)(Ap + 4);
    float4 pb0 = *(const float4*)(Bp + 0);
    float4 pb1 = *(const float4*)(Bp + 4);

    for (int k0 = 0; k0 < K; k0 += 16) {
        __syncthreads();
        // store prefetched tile (transposed, tf32-rounded)
        float* as = &As[lc * SMS + lrow];
        as[0 * SMS] = __uint_as_float(f2tf(pa0.x));
        as[1 * SMS] = __uint_as_float(f2tf(pa0.y));
        as[2 * SMS] = __uint_as_float(f2tf(pa0.z));
        as[3 * SMS] = __uint_as_float(f2tf(pa0.w));
        as[4 * SMS] = __uint_as_float(f2tf(pa1.x));
        as[5 * SMS] = __uint_as_float(f2tf(pa1.y));
        as[6 * SMS] = __uint_as_float(f2tf(pa1.z));
        as[7 * SMS] = __uint_as_float(f2tf(pa1.w));
        float* bs = &Bs[lc * SMS + lrow];
        bs[0 * SMS] = __uint_as_float(f2tf(pb0.x));
        bs[1 * SMS] = __uint_as_float(f2tf(pb0.y));
        bs[2 * SMS] = __uint_as_float(f2tf(pb0.z));
        bs[3 * SMS] = __uint_as_float(f2tf(pb0.w));
        bs[4 * SMS] = __uint_as_float(f2tf(pb1.x));
        bs[5 * SMS] = __uint_as_float(f2tf(pb1.y));
        bs[6 * SMS] = __uint_as_float(f2tf(pb1.z));
        bs[7 * SMS] = __uint_as_float(f2tf(pb1.w));
        __syncthreads();

        if (k0 + 16 < K) {   // prefetch next tile
            pa0 = *(const float4*)(Ap + k0 + 16);
            pa1 = *(const float4*)(Ap + k0 + 20);
            pb0 = *(const float4*)(Bp + k0 + 16);
            pb1 = *(const float4*)(Bp + k0 + 20);
        }

#pragma unroll
        for (int ks = 0; ks < 2; ++ks) {
            const int kk = ks * 8;
            unsigned af[2][4];
#pragma unroll
            for (int i = 0; i < 2; ++i) {
                const float* ab = &As[(kk + c) * SMS + wm * 32 + i * 16 + g];
                af[i][0] = __float_as_uint(ab[0]);
                af[i][1] = __float_as_uint(ab[8]);
                af[i][2] = __float_as_uint(ab[4 * SMS]);
                af[i][3] = __float_as_uint(ab[4 * SMS + 8]);
            }
#pragma unroll
            for (int j = 0; j < 8; ++j) {
                const float* bb = &Bs[(kk + c) * SMS + wn * 64 + j * 8 + g];
                unsigned b0 = __float_as_uint(bb[0]);
                unsigned b1 = __float_as_uint(bb[4 * SMS]);
                mma_tf32(acc[0][j], af[0], b0, b1);
                mma_tf32(acc[1][j], af[1], b0, b1);
            }
        }
    }

    // Epilogue: + bias, optional Q scaling, float2 stores
#pragma unroll
    for (int j = 0; j < 8; ++j) {
        const int col = n0 + wn * 64 + j * 8 + c * 2;
        float b0 = bias[col], b1 = bias[col + 1];
        float q0 = 1.f, q1 = 1.f;
        if (APPLY_QSCALE && col < H_ * HD_) {
            q0 = g_qscale[col % HD_];
            q1 = g_qscale[(col + 1) % HD_];
        }
#pragma unroll
        for (int i = 0; i < 2; ++i) {
            const int r0 = m0 + wm * 32 + i * 16 + g;
            float2 o0, o1;
            o0.x = (acc[i][j][0] + b0) * q0;
            o0.y = (acc[i][j][1] + b1) * q1;
            o1.x = (acc[i][j][2] + b0) * q0;
            o1.y = (acc[i][j][3] + b1) * q1;
            *(float2*)&C[(size_t)r0 * N + col]       = o0;
            *(float2*)&C[(size_t)(r0 + 8) * N + col] = o1;
        }
    }
}

// ---------------------------------------------------------------------------
// Causal flash attention, fp32. One thread per query row (online softmax is
// thread-local). BQ=128 queries/block, BK=32 keys per tile. Q/K/V read from
// g_qkv ([b,s,3*H*HD] layout, Q already scaled). Output to g_attn [b,s,H*HD].
// ---------------------------------------------------------------------------
__global__ __launch_bounds__(128, 3)
void flash_kernel() {
    extern __shared__ float smem[];
    float4* q_s = (float4*)smem;        // [128][21]
    float4* k_s = q_s + 128 * 21;       // [32][21]
    float4* v_s = k_s + 32 * 21;        // [32][21]

    const int t  = threadIdx.x;
    const int qt = gridDim.x - 1 - blockIdx.x;   // heavy blocks first
    const int q0 = qt * 128;
    const int h  = blockIdx.y;
    const int b  = blockIdx.z;

    const float4* qkv4 = (const float4*)g_qkv;   // row stride 960

    for (int i = t; i < 128 * 20; i += 128) {
        int r = i / 20, c = i % 20;
        q_s[r * 21 + c] = qkv4[(size_t)(b * S_ + q0 + r) * 960 + h * 20 + c];
    }

    const int qi = q0 + t;
    float m = -INFINITY, l = 0.f;
    float4 acc[20];
#pragma unroll
    for (int d = 0; d < 20; ++d) acc[d] = make_float4(0.f, 0.f, 0.f, 0.f);

    for (int k0 = 0; k0 < q0 + 128; k0 += 32) {
        __syncthreads();
        for (int i = t; i < 32 * 20; i += 128) {
            int r = i / 20, c = i % 20;
            size_t base = (size_t)(b * S_ + k0 + r) * 960 + h * 20 + c;
            k_s[r * 21 + c] = qkv4[base + 320];
            v_s[r * 21 + c] = qkv4[base + 640];
        }
        __syncthreads();

        if (k0 <= qi) {
            float sc[32];
#pragma unroll
            for (int j = 0; j < 32; ++j) sc[j] = 0.f;
#pragma unroll 4
            for (int d = 0; d < 20; ++d) {
                float4 q4 = q_s[t * 21 + d];
#pragma unroll
                for (int j = 0; j < 32; ++j) {
                    float4 k4 = k_s[j * 21 + d];
                    sc[j] += q4.x * k4.x + q4.y * k4.y;
                    sc[j] += q4.z * k4.z + q4.w * k4.w;
                }
            }
            float tmax = -INFINITY;
#pragma unroll
            for (int j = 0; j < 32; ++j) {
                if (k0 + j > qi) sc[j] = -INFINITY;
                tmax = fmaxf(tmax, sc[j]);
            }
            float m_new = fmaxf(m, tmax);
            float corr = __expf(m - m_new);
            float lsum = 0.f;
#pragma unroll
            for (int j = 0; j < 32; ++j) {
                float p = __expf(sc[j] - m_new);
                sc[j] = p;
                lsum += p;
            }
            l = l * corr + lsum;
            m = m_new;
#pragma unroll
            for (int d = 0; d < 20; ++d) {
                acc[d].x *= corr; acc[d].y *= corr;
                acc[d].z *= corr; acc[d].w *= corr;
            }
#pragma unroll 4
            for (int j = 0; j < 32; ++j) {
                float p = sc[j];
#pragma unroll
                for (int d = 0; d < 20; ++d) {
                    float4 v4 = v_s[j * 21 + d];
                    acc[d].x += p * v4.x; acc[d].y += p * v4.y;
                    acc[d].z += p * v4.z; acc[d].w += p * v4.w;
                }
            }
        }
    }

    const float inv = 1.f / l;
    float4* out4 = (float4*)g_attn;   // row stride 320
    size_t obase = (size_t)(b * S_ + qi) * 320 + h * 20;
#pragma unroll
    for (int d = 0; d < 20; ++d) {
        out4[obase + d] = make_float4(acc[d].x * inv, acc[d].y * inv,
                                      acc[d].z * inv, acc[d].w * inv);
    }
}

// ---------------------------------------------------------------------------
// Launch
// ---------------------------------------------------------------------------
extern "C" void kernel_launch(void* const* d_in, const int* in_sizes, int n_in,
                              void* d_out, int out_size) {
    const float* hidden  = (const float*)d_in[0];
    // d_in[1] = attention_mask: pure causal, implemented structurally
    const float* scaling = (const float*)d_in[2];
    const float* qkv_w   = (const float*)d_in[3];
    const float* qkv_b   = (const float*)d_in[4];
    const float* o_w     = (const float*)d_in[5];
    const float* o_b     = (const float*)d_in[6];
    float* out = (float*)d_out;

    void* p_qkv = nullptr;
    void* p_attn = nullptr;
    cudaGetSymbolAddress(&p_qkv, g_qkv);
    cudaGetSymbolAddress(&p_attn, g_attn);

    qscale_kernel<<<1, 128>>>(scaling);

    // QKV projection: [8192,1280] x [3840,1280]^T (+bias, Q-scale epilogue)
    gemm_tf32<1><<<dim3(NQKV / 128, (B_ * S_) / 128), 256>>>(
        hidden, qkv_w, qkv_b, (float*)p_qkv, B_ * S_, NQKV, D_);

    // Causal flash attention
    const int smem_bytes = (128 * 21 + 32 * 21 + 32 * 21) * 16;  // 64512 B
    cudaFuncSetAttribute(flash_kernel,
                         cudaFuncAttributeMaxDynamicSharedMemorySize, smem_bytes);
    flash_kernel<<<dim3(S_ / 128, H_, B_), 128, smem_bytes>>>();

    // Output projection: [8192,1280] x [1280,1280]^T (+bias)
    gemm_tf32<0><<<dim3(D_ / 128, (B_ * S_) / 128), 256>>>(
        (const float*)p_attn, o_w, o_b, out, B_ * S_, D_, D_);
}

// round 6
// speedup vs baseline: 2.4241x; 1.6513x over previous
#include <cuda_runtime.h>
#include <math.h>

#define B_  4
#define S_  2048
#define D_  1280
#define H_  16
#define HD_ 80
#define NQKV (3 * H_ * HD_)   // 3840

// Scratch (allocation-free rule: __device__ globals)
__device__ float g_qkv[(size_t)B_ * S_ * NQKV];        // 126 MB
__device__ float g_attn[(size_t)B_ * S_ * H_ * HD_];   // 42 MB
__device__ float g_qscale[HD_];

// ---------------------------------------------------------------------------
// Helpers: tf32 rounding + mma
// ---------------------------------------------------------------------------
__device__ __forceinline__ unsigned f2tf(float x) {
    unsigned r;
    asm("cvt.rna.tf32.f32 %0, %1;" : "=r"(r) : "f"(x));
    return r;
}
__device__ __forceinline__ float f2tff(float x) {
    return __uint_as_float(f2tf(x));
}
__device__ __forceinline__ void mma_tf32(float* d, const unsigned* a,
                                         unsigned b0, unsigned b1) {
    asm volatile(
        "mma.sync.aligned.m16n8k8.row.col.f32.tf32.tf32.f32 "
        "{%0,%1,%2,%3}, {%4,%5,%6,%7}, {%8,%9}, {%0,%1,%2,%3};"
        : "+f"(d[0]), "+f"(d[1]), "+f"(d[2]), "+f"(d[3])
        : "r"(a[0]), "r"(a[1]), "r"(a[2]), "r"(a[3]), "r"(b0), "r"(b1));
}

// ---------------------------------------------------------------------------
// Per-dim query scale: softplus(scaling) * log2(e) / sqrt(HD)
// ---------------------------------------------------------------------------
__global__ void qscale_kernel(const float* __restrict__ scaling) {
    int i = threadIdx.x;
    if (i < HD_) {
        float x = scaling[i];
        float sp = (x > 20.f) ? x : log1pf(expf(x));
        g_qscale[i] = sp * 1.4426950408889634f * rsqrtf((float)HD_);
    }
}

// ---------------------------------------------------------------------------
// TF32 tensor-core GEMM: C = A·B^T + bias  (both K-major)
// 128x128 tile, KT=16, 256 threads, warp tile 32x64, m16n8k8.tf32.
// ---------------------------------------------------------------------------
#define SMS 136

template <int APPLY_QSCALE>
__global__ __launch_bounds__(256, 2)
void gemm_tf32(const float* __restrict__ A, const float* __restrict__ Bm,
               const float* __restrict__ bias, float* __restrict__ C,
               int M, int N, int K) {
    __shared__ float As[16 * SMS];
    __shared__ float Bs[16 * SMS];

    const int tid  = threadIdx.x;
    const int lane = tid & 31;
    const int wid  = tid >> 5;
    const int wm   = wid & 3;
    const int wn   = wid >> 2;
    const int g    = lane >> 2;
    const int c    = lane & 3;

    const int m0 = blockIdx.y * 128;
    const int n0 = blockIdx.x * 128;

    const int lrow = tid >> 1;
    const int lc   = (tid & 1) * 8;

    const float* Ap = A  + (size_t)(m0 + lrow) * K + lc;
    const float* Bp = Bm + (size_t)(n0 + lrow) * K + lc;

    float acc[2][8][4];
#pragma unroll
    for (int i = 0; i < 2; ++i)
#pragma unroll
        for (int j = 0; j < 8; ++j)
#pragma unroll
            for (int q = 0; q < 4; ++q) acc[i][j][q] = 0.f;

    float4 pa0 = *(const float4*)(Ap + 0);
    float4 pa1 = *(const float4*)(Ap + 4);
    float4 pb0 = *(const float4*)(Bp + 0);
    float4 pb1 = *(const float4*)(Bp + 4);

    for (int k0 = 0; k0 < K; k0 += 16) {
        __syncthreads();
        float* as = &As[lc * SMS + lrow];
        as[0 * SMS] = f2tff(pa0.x); as[1 * SMS] = f2tff(pa0.y);
        as[2 * SMS] = f2tff(pa0.z); as[3 * SMS] = f2tff(pa0.w);
        as[4 * SMS] = f2tff(pa1.x); as[5 * SMS] = f2tff(pa1.y);
        as[6 * SMS] = f2tff(pa1.z); as[7 * SMS] = f2tff(pa1.w);
        float* bs = &Bs[lc * SMS + lrow];
        bs[0 * SMS] = f2tff(pb0.x); bs[1 * SMS] = f2tff(pb0.y);
        bs[2 * SMS] = f2tff(pb0.z); bs[3 * SMS] = f2tff(pb0.w);
        bs[4 * SMS] = f2tff(pb1.x); bs[5 * SMS] = f2tff(pb1.y);
        bs[6 * SMS] = f2tff(pb1.z); bs[7 * SMS] = f2tff(pb1.w);
        __syncthreads();

        if (k0 + 16 < K) {
            pa0 = *(const float4*)(Ap + k0 + 16);
            pa1 = *(const float4*)(Ap + k0 + 20);
            pb0 = *(const float4*)(Bp + k0 + 16);
            pb1 = *(const float4*)(Bp + k0 + 20);
        }

#pragma unroll
        for (int ks = 0; ks < 2; ++ks) {
            const int kk = ks * 8;
            unsigned af[2][4];
#pragma unroll
            for (int i = 0; i < 2; ++i) {
                const float* ab = &As[(kk + c) * SMS + wm * 32 + i * 16 + g];
                af[i][0] = __float_as_uint(ab[0]);
                af[i][1] = __float_as_uint(ab[8]);
                af[i][2] = __float_as_uint(ab[4 * SMS]);
                af[i][3] = __float_as_uint(ab[4 * SMS + 8]);
            }
#pragma unroll
            for (int j = 0; j < 8; ++j) {
                const float* bb = &Bs[(kk + c) * SMS + wn * 64 + j * 8 + g];
                unsigned b0 = __float_as_uint(bb[0]);
                unsigned b1 = __float_as_uint(bb[4 * SMS]);
                mma_tf32(acc[0][j], af[0], b0, b1);
                mma_tf32(acc[1][j], af[1], b0, b1);
            }
        }
    }

#pragma unroll
    for (int j = 0; j < 8; ++j) {
        const int col = n0 + wn * 64 + j * 8 + c * 2;
        float b0 = bias[col], b1 = bias[col + 1];
        float q0 = 1.f, q1 = 1.f;
        if (APPLY_QSCALE && col < H_ * HD_) {
            q0 = g_qscale[col % HD_];
            q1 = g_qscale[(col + 1) % HD_];
        }
#pragma unroll
        for (int i = 0; i < 2; ++i) {
            const int r0 = m0 + wm * 32 + i * 16 + g;
            float2 o0, o1;
            o0.x = (acc[i][j][0] + b0) * q0;
            o0.y = (acc[i][j][1] + b1) * q1;
            o1.x = (acc[i][j][2] + b0) * q0;
            o1.y = (acc[i][j][3] + b1) * q1;
            *(float2*)&C[(size_t)r0 * N + col]       = o0;
            *(float2*)&C[(size_t)(r0 + 8) * N + col] = o1;
        }
    }
}

// ---------------------------------------------------------------------------
// Tensor-core causal flash attention (tf32 HMMA, FA2-style).
// BQ=64 (4 warps x 16 rows), BK=64. K/V staged fragment-major (stride 21,
// conflict-free scalar LDS). Vf sized for n=0..79 (80*4*21 floats) — this
// was the R5 overflow bug. P re-fragmented via warp-private smem (stride 68)
// reusing the Q staging region. Softmax fp32, quad shuffles.
// grid = (S/64 [reversed], H, B), block = 128.
// ---------------------------------------------------------------------------
#define KV_ST 21
#define P_ST  68
#define QS_ST 84
#define QS_FLOATS (64 * QS_ST)          // 5376
#define KF_FLOATS (64 * 4 * KV_ST)      // 5376
#define VF_FLOATS (80 * 4 * KV_ST)      // 6720  (n-indexed: 80 features!)
#define FL_SMEM_FLOATS (QS_FLOATS + KF_FLOATS + VF_FLOATS)   // 17472

__global__ __launch_bounds__(128, 2)
void flash_tc() {
    extern __shared__ float sm[];
    float* Qs = sm;                     // [64][84]; reused as P
    float* Kf = sm + QS_FLOATS;         // 5376 floats
    float* Vf = Kf + KF_FLOATS;         // 6720 floats

    const int t    = threadIdx.x;
    const int lane = t & 31;
    const int wq   = t >> 5;               // warp 0..3 -> rows wq*16..+15
    const int g    = lane >> 2;            // 0..7
    const int c    = lane & 3;             // 0..3
    const int qt   = gridDim.x - 1 - blockIdx.x;   // heavy blocks first
    const int q0   = qt * 64;
    const int h    = blockIdx.y;
    const int b    = blockIdx.z;

    const float4* qkv4 = (const float4*)g_qkv;     // row stride 960

    // Stage Q (tf32-rounded) into Qs[64][84]
    for (int i = t; i < 64 * 20; i += 128) {
        int r = i / 20, q = i % 20;
        float4 v = qkv4[(size_t)(b * S_ + q0 + r) * 960 + h * 20 + q];
        float* dst = &Qs[r * QS_ST + q * 4];
        dst[0] = f2tff(v.x); dst[1] = f2tff(v.y);
        dst[2] = f2tff(v.z); dst[3] = f2tff(v.w);
    }
    __syncthreads();

    // Q fragments (A layout): a0=Q[g][8kt+c], a1=Q[g+8][..], a2/a3 = +4 col
    unsigned qf[10][4];
#pragma unroll
    for (int kt = 0; kt < 10; ++kt) {
        const float* qp = &Qs[(wq * 16 + g) * QS_ST + kt * 8 + c];
        qf[kt][0] = __float_as_uint(qp[0]);
        qf[kt][1] = __float_as_uint(qp[8 * QS_ST]);
        qf[kt][2] = __float_as_uint(qp[4]);
        qf[kt][3] = __float_as_uint(qp[8 * QS_ST + 4]);
    }

    float m0 = -INFINITY, m1 = -INFINITY, l0 = 0.f, l1 = 0.f;
    float o[10][4];
#pragma unroll
    for (int j = 0; j < 10; ++j)
#pragma unroll
        for (int q = 0; q < 4; ++q) o[j][q] = 0.f;

    float* Pw = sm + wq * (16 * P_ST);   // warp-private, overlaps Qs
                                         // (safe: qf in regs before loop, and
                                         // loop-head __syncthreads orders it)

    const int ntiles = qt + 1;
    for (int kt0 = 0; kt0 < ntiles; ++kt0) {
        const int k0 = kt0 * 64;
        __syncthreads();
        // Load K,V tiles into fragment-major smem (tf32-rounded)
        for (int i = t; i < 64 * 20; i += 128) {
            int r = i / 20, q = i % 20;
            size_t base = (size_t)(b * S_ + k0 + r) * 960 + h * 20 + q;
            float4 kv = qkv4[base + 320];
            // K[r][4q+e] -> Kf[(r*4+e)*21 + q]
            float* kd = &Kf[(r * 4) * KV_ST + q];
            kd[0 * KV_ST] = f2tff(kv.x);
            kd[1 * KV_ST] = f2tff(kv.y);
            kd[2 * KV_ST] = f2tff(kv.z);
            kd[3 * KV_ST] = f2tff(kv.w);
            float4 vv = qkv4[base + 640];
            // V[r][n] -> Vf[(n*4 + r%4)*21 + r/4]   (n = 4q+e, 0..79)
            int vb = (r & 3) * KV_ST + (r >> 2);
            Vf[(4 * q + 0) * 4 * KV_ST + vb] = f2tff(vv.x);
            Vf[(4 * q + 1) * 4 * KV_ST + vb] = f2tff(vv.y);
            Vf[(4 * q + 2) * 4 * KV_ST + vb] = f2tff(vv.z);
            Vf[(4 * q + 3) * 4 * KV_ST + vb] = f2tff(vv.w);
        }
        __syncthreads();

        // ---- S = Q K^T (8 independent accumulator chains) ----
        float s[8][4];
#pragma unroll
        for (int j = 0; j < 8; ++j)
#pragma unroll
            for (int q = 0; q < 4; ++q) s[j][q] = 0.f;
#pragma unroll
        for (int kt = 0; kt < 10; ++kt)
#pragma unroll
            for (int j = 0; j < 8; ++j) {
                const float* kb = &Kf[((j * 8 + g) * 4 + c) * KV_ST + 2 * kt];
                mma_tf32(s[j], qf[kt],
                         __float_as_uint(kb[0]), __float_as_uint(kb[1]));
            }

        // ---- causal mask (diagonal tile only) ----
        if (k0 == q0) {
            const int row0 = wq * 16 + g;
#pragma unroll
            for (int j = 0; j < 8; ++j) {
                const int col = j * 8 + 2 * c;
                if (col     > row0)     s[j][0] = -INFINITY;
                if (col + 1 > row0)     s[j][1] = -INFINITY;
                if (col     > row0 + 8) s[j][2] = -INFINITY;
                if (col + 1 > row0 + 8) s[j][3] = -INFINITY;
            }
        }

        // ---- online softmax (rows g and g+8; quad shuffles) ----
        float tm0 = -INFINITY, tm1 = -INFINITY;
#pragma unroll
        for (int j = 0; j < 8; ++j) {
            tm0 = fmaxf(tm0, fmaxf(s[j][0], s[j][1]));
            tm1 = fmaxf(tm1, fmaxf(s[j][2], s[j][3]));
        }
        tm0 = fmaxf(tm0, __shfl_xor_sync(0xffffffff, tm0, 1));
        tm0 = fmaxf(tm0, __shfl_xor_sync(0xffffffff, tm0, 2));
        tm1 = fmaxf(tm1, __shfl_xor_sync(0xffffffff, tm1, 1));
        tm1 = fmaxf(tm1, __shfl_xor_sync(0xffffffff, tm1, 2));
        float nm0 = fmaxf(m0, tm0), nm1 = fmaxf(m1, tm1);
        float cr0 = __expf(m0 - nm0), cr1 = __expf(m1 - nm1);
        m0 = nm0; m1 = nm1;
        float ls0 = 0.f, ls1 = 0.f;
#pragma unroll
        for (int j = 0; j < 8; ++j) {
            s[j][0] = __expf(s[j][0] - m0);
            s[j][1] = __expf(s[j][1] - m0);
            s[j][2] = __expf(s[j][2] - m1);
            s[j][3] = __expf(s[j][3] - m1);
            ls0 += s[j][0] + s[j][1];
            ls1 += s[j][2] + s[j][3];
        }
        ls0 += __shfl_xor_sync(0xffffffff, ls0, 1);
        ls0 += __shfl_xor_sync(0xffffffff, ls0, 2);
        ls1 += __shfl_xor_sync(0xffffffff, ls1, 1);
        ls1 += __shfl_xor_sync(0xffffffff, ls1, 2);
        l0 = l0 * cr0 + ls0;
        l1 = l1 * cr1 + ls1;
#pragma unroll
        for (int j = 0; j < 10; ++j) {
            o[j][0] *= cr0; o[j][1] *= cr0;
            o[j][2] *= cr1; o[j][3] *= cr1;
        }

        // ---- P round trip: C-fragment -> warp smem -> A-fragment ----
        __syncwarp();
#pragma unroll
        for (int j = 0; j < 8; ++j) {
            *(float2*)&Pw[g * P_ST + j * 8 + 2 * c] =
                make_float2(f2tff(s[j][0]), f2tff(s[j][1]));
            *(float2*)&Pw[(g + 8) * P_ST + j * 8 + 2 * c] =
                make_float2(f2tff(s[j][2]), f2tff(s[j][3]));
        }
        __syncwarp();
        unsigned pa[8][4];
#pragma unroll
        for (int kt = 0; kt < 8; ++kt) {
            const float* pp = &Pw[g * P_ST + kt * 8 + c];
            pa[kt][0] = __float_as_uint(pp[0]);
            pa[kt][1] = __float_as_uint(pp[8 * P_ST]);
            pa[kt][2] = __float_as_uint(pp[4]);
            pa[kt][3] = __float_as_uint(pp[8 * P_ST + 4]);
        }

        // ---- O += P V (10 independent chains) ----
#pragma unroll
        for (int kt = 0; kt < 8; ++kt)
#pragma unroll
            for (int j = 0; j < 10; ++j) {
                const float* vb = &Vf[((j * 8 + g) * 4 + c) * KV_ST + 2 * kt];
                mma_tf32(o[j], pa[kt],
                         __float_as_uint(vb[0]), __float_as_uint(vb[1]));
            }
    }

    // ---- epilogue: normalize, write g_attn ----
    const float inv0 = 1.f / l0, inv1 = 1.f / l1;
    const int r0 = q0 + wq * 16 + g;
    float* outp = g_attn + (size_t)(b * S_ + r0) * (H_ * HD_) + h * HD_;
#pragma unroll
    for (int j = 0; j < 10; ++j) {
        *(float2*)&outp[j * 8 + 2 * c] =
            make_float2(o[j][0] * inv0, o[j][1] * inv0);
        *(float2*)&outp[(size_t)8 * (H_ * HD_) + j * 8 + 2 * c] =
            make_float2(o[j][2] * inv1, o[j][3] * inv1);
    }
}

// ---------------------------------------------------------------------------
// Launch
// ---------------------------------------------------------------------------
extern "C" void kernel_launch(void* const* d_in, const int* in_sizes, int n_in,
                              void* d_out, int out_size) {
    const float* hidden  = (const float*)d_in[0];
    // d_in[1] = attention_mask: pure causal, implemented structurally
    const float* scaling = (const float*)d_in[2];
    const float* qkv_w   = (const float*)d_in[3];
    const float* qkv_b   = (const float*)d_in[4];
    const float* o_w     = (const float*)d_in[5];
    const float* o_b     = (const float*)d_in[6];
    float* out = (float*)d_out;

    void* p_qkv = nullptr;
    void* p_attn = nullptr;
    cudaGetSymbolAddress(&p_qkv, g_qkv);
    cudaGetSymbolAddress(&p_attn, g_attn);

    qscale_kernel<<<1, 128>>>(scaling);

    // QKV projection: [8192,1280] x [3840,1280]^T (+bias, Q-scale epilogue)
    gemm_tf32<1><<<dim3(NQKV / 128, (B_ * S_) / 128), 256>>>(
        hidden, qkv_w, qkv_b, (float*)p_qkv, B_ * S_, NQKV, D_);

    // Tensor-core causal flash attention
    const int smem_bytes = FL_SMEM_FLOATS * 4;   // 69888 B
    cudaFuncSetAttribute(flash_tc,
                         cudaFuncAttributeMaxDynamicSharedMemorySize, smem_bytes);
    flash_tc<<<dim3(S_ / 64, H_, B_), 128, smem_bytes>>>();

    // Output projection: [8192,1280] x [1280,1280]^T (+bias)
    gemm_tf32<0><<<dim3(D_ / 128, (B_ * S_) / 128), 256>>>(
        (const float*)p_attn, o_w, o_b, out, B_ * S_, D_, D_);
}